// round 10
// baseline (speedup 1.0000x reference)
#include <cuda_runtime.h>
#include <cuda_bf16.h>
#include <cuda_fp16.h>
#include <math.h>
#include <stdint.h>

#define HID  128
#define NMAX 50000
#define EMAX 800000
#define SCAN_CHUNK 1024
#define WSTR 136          // padded row stride in bf16 halves (272B, 16B-aligned)

// ---------------- device scratch ----------------
__device__ float  g_q[NMAX * HID];        // fp32, head-major
// interleaved k/v, fp16: per node 32 chunks of 16B = {k[4i..4i+3], v[4i..4i+3]}
__device__ __half g_kv[NMAX * 256];
__device__ int   g_cnt[NMAX];
__device__ int   g_rp[NMAX + 1];
__device__ int   g_col[EMAX];
__device__ int   g_bsum[64];
__device__ uint16_t g_wh[4 * 128 * WSTR];
__device__ uint16_t g_wl[4 * 128 * WSTR];
__device__ float    g_biasp[4 * 128];

__device__ __forceinline__ int permc(int c)  { return ((c & 7) << 4) | (c >> 3); }
__device__ __forceinline__ int ipermc(int j) { return ((j & 15) << 3) | (j >> 4); }

__device__ __forceinline__ uint32_t smem_u32(const void* p) {
    uint32_t a;
    asm("{ .reg .u64 t; cvta.to.shared.u64 t, %1; cvt.u32.u64 %0, t; }" : "=r"(a) : "l"(p));
    return a;
}
#define LDSM_X4(r0, r1, r2, r3, addr) \
    asm volatile("ldmatrix.sync.aligned.m8n8.x4.shared.b16 {%0,%1,%2,%3}, [%4];" \
                 : "=r"(r0), "=r"(r1), "=r"(r2), "=r"(r3) : "r"(addr))
#define MMA_BF16(c, a, b) \
    asm volatile("mma.sync.aligned.m16n8k16.row.col.f32.bf16.bf16.f32 " \
                 "{%0,%1,%2,%3}, {%4,%5,%6,%7}, {%8,%9}, {%0,%1,%2,%3};" \
                 : "+f"((c)[0]), "+f"((c)[1]), "+f"((c)[2]), "+f"((c)[3]) \
                 : "r"((a)[0]), "r"((a)[1]), "r"((a)[2]), "r"((a)[3]), \
                   "r"((b)[0]), "r"((b)[1]))

// smem layout shared by both mma kernels
#define SM_TILE  (128 * WSTR * 2)
#define SM_AHI   1024
#define SM_ALO   (SM_AHI + SM_TILE)
#define SM_WHI   (SM_ALO + SM_TILE)
#define SM_WLO   (SM_WHI + SM_TILE)
#define SM_TOTAL (SM_WLO + SM_TILE)

// ---------------- weight prep ----------------
__global__ void prep_w_kernel(const float* __restrict__ Wq, const float* __restrict__ bq,
                              const float* __restrict__ Wk, const float* __restrict__ bk,
                              const float* __restrict__ Wv, const float* __restrict__ bv,
                              const float* __restrict__ Wo, const float* __restrict__ bo) {
    int s = blockIdx.x;
    const float* W = (s == 0) ? Wq : (s == 1) ? Wk : (s == 2) ? Wv : Wo;
    const float* b = (s == 0) ? bq : (s == 1) ? bk : (s == 2) ? bv : bo;
    uint16_t* dh = g_wh + (size_t)s * 128 * WSTR;
    uint16_t* dl = g_wl + (size_t)s * 128 * WSTR;

    for (int idx = threadIdx.x; idx < 128 * 128; idx += blockDim.x) {
        int j = idx >> 7, k = idx & 127;
        float val; int dc;
        if (s < 3) { val = W[ipermc(j) * HID + k]; dc = k; }
        else       { val = W[j * HID + k];         dc = permc(k); }
        __nv_bfloat16 hi = __float2bfloat16(val);
        __nv_bfloat16 lo = __float2bfloat16(val - __bfloat162float(hi));
        dh[j * WSTR + dc] = __bfloat16_as_ushort(hi);
        dl[j * WSTR + dc] = __bfloat16_as_ushort(lo);
    }
    if (threadIdx.x < 128) {
        int j = threadIdx.x;
        g_biasp[s * 128 + j] = (s < 3) ? b[ipermc(j)] : b[j];
    }
}

// ---------------- shared device helpers for the mma mainloop --------------
struct MmaCtx {
    uint32_t aAddrH[2], aAddrL[2], bAddrH[2], bAddrL[2];
    int Rw, cb;
};
__device__ __forceinline__ void mma_setup(MmaCtx& cx, uint32_t sb, int wid, int lane) {
    cx.Rw = (wid & 3) * 32;
    cx.cb = (wid >> 2) * 32;
    const int a_r = cx.Rw + (lane & 15);
    const int a_k = (lane >> 4) << 3;
#pragma unroll
    for (int mi = 0; mi < 2; mi++) {
        uint32_t off = (uint32_t)((a_r + mi * 16) * WSTR + a_k) * 2;
        cx.aAddrH[mi] = sb + SM_AHI + off;
        cx.aAddrL[mi] = sb + SM_ALO + off;
    }
    const int b_r = (lane & 7) + ((lane >> 4) << 3);
    const int b_k = ((lane >> 3) & 1) << 3;
#pragma unroll
    for (int g = 0; g < 2; g++) {
        uint32_t off = (uint32_t)((cx.cb + g * 16 + b_r) * WSTR + b_k) * 2;
        cx.bAddrH[g] = sb + SM_WHI + off;
        cx.bAddrL[g] = sb + SM_WLO + off;
    }
}
__device__ __forceinline__ void mma_mainloop(const MmaCtx& cx, float acc[2][4][4]) {
#pragma unroll
    for (int mi = 0; mi < 2; mi++)
#pragma unroll
        for (int ni = 0; ni < 4; ni++)
#pragma unroll
            for (int r = 0; r < 4; r++) acc[mi][ni][r] = 0.f;
#pragma unroll 2
    for (int k = 0; k < 8; k++) {
        const uint32_t ko = k * 32;
        uint32_t ah[2][4], al[2][4], bh[4][2], bl[4][2];
#pragma unroll
        for (int mi = 0; mi < 2; mi++) {
            LDSM_X4(ah[mi][0], ah[mi][1], ah[mi][2], ah[mi][3], cx.aAddrH[mi] + ko);
            LDSM_X4(al[mi][0], al[mi][1], al[mi][2], al[mi][3], cx.aAddrL[mi] + ko);
        }
#pragma unroll
        for (int g = 0; g < 2; g++) {
            LDSM_X4(bh[2 * g][0], bh[2 * g][1], bh[2 * g + 1][0], bh[2 * g + 1][1], cx.bAddrH[g] + ko);
            LDSM_X4(bl[2 * g][0], bl[2 * g][1], bl[2 * g + 1][0], bl[2 * g + 1][1], cx.bAddrL[g] + ko);
        }
#pragma unroll
        for (int mi = 0; mi < 2; mi++)
#pragma unroll
            for (int ni = 0; ni < 4; ni++) {
                MMA_BF16(acc[mi][ni], ah[mi], bh[ni]);
                MMA_BF16(acc[mi][ni], ah[mi], bl[ni]);
                MMA_BF16(acc[mi][ni], al[mi], bh[ni]);
            }
    }
}
__device__ __forceinline__ void split_store_pair(uint16_t* hp, uint16_t* lp, float4 x) {
    __nv_bfloat16 h0 = __float2bfloat16(x.x), h1 = __float2bfloat16(x.y);
    __nv_bfloat16 h2 = __float2bfloat16(x.z), h3 = __float2bfloat16(x.w);
    __nv_bfloat16 l0 = __float2bfloat16(x.x - __bfloat162float(h0));
    __nv_bfloat16 l1 = __float2bfloat16(x.y - __bfloat162float(h1));
    __nv_bfloat16 l2 = __float2bfloat16(x.z - __bfloat162float(h2));
    __nv_bfloat16 l3 = __float2bfloat16(x.w - __bfloat162float(h3));
    uint32_t hA = ((uint32_t)__bfloat16_as_ushort(h1) << 16) | __bfloat16_as_ushort(h0);
    uint32_t hB = ((uint32_t)__bfloat16_as_ushort(h3) << 16) | __bfloat16_as_ushort(h2);
    uint32_t lA = ((uint32_t)__bfloat16_as_ushort(l1) << 16) | __bfloat16_as_ushort(l0);
    uint32_t lB = ((uint32_t)__bfloat16_as_ushort(l3) << 16) | __bfloat16_as_ushort(l2);
    *(uint2*)hp = make_uint2(hA, hB);
    *(uint2*)lp = make_uint2(lA, lB);
}

// ---------------- qkv GEMM (modes 0..2 via blockIdx.y) --------------------
__global__ __launch_bounds__(512, 1)
void mma_gemm_kernel(const float* __restrict__ A_ext, int n) {
    extern __shared__ char smem[];
    const uint32_t sb = smem_u32(smem);
    const int tid = threadIdx.x;
    const int wid = tid >> 5, lane = tid & 31;
    const int mode = blockIdx.y;
    const int row0 = blockIdx.x * 128;

    if (tid < 128) *(float*)(smem + tid * 4) = g_biasp[mode * 128 + tid];

    {
        const float4* sh = (const float4*)(g_wh + (size_t)mode * 128 * WSTR);
        const float4* sl = (const float4*)(g_wl + (size_t)mode * 128 * WSTR);
        float4* dh = (float4*)(smem + SM_WHI);
        float4* dl = (float4*)(smem + SM_WLO);
#pragma unroll
        for (int i = 0; i < 5; i++) {
            int idx = tid + 512 * i;
            if (idx < 2176) { dh[idx] = sh[idx]; dl[idx] = sl[idx]; }
        }
    }
    {
        int r = tid >> 2, hf = tid & 3;
        bool ok = (row0 + r) < n;
        const float4* arow = (const float4*)(A_ext + (size_t)(row0 + r) * HID) + hf * 8;
        uint16_t* ahp = (uint16_t*)(smem + SM_AHI) + r * WSTR + hf * 32;
        uint16_t* alp = (uint16_t*)(smem + SM_ALO) + r * WSTR + hf * 32;
#pragma unroll
        for (int i = 0; i < 8; i++) {
            float4 x = ok ? arow[i] : make_float4(0.f, 0.f, 0.f, 0.f);
            split_store_pair(ahp + i * 4, alp + i * 4, x);
        }
    }
    __syncthreads();

    MmaCtx cx;
    mma_setup(cx, sb, wid, lane);
    float acc[2][4][4];
    mma_mainloop(cx, acc);

    const float* bs = (const float*)smem;
    const float scale = (mode == 0) ? 0.25f : 1.0f;
#pragma unroll
    for (int mi = 0; mi < 2; mi++) {
        int rA = row0 + cx.Rw + mi * 16 + (lane >> 2);
        int rB = rA + 8;
#pragma unroll
        for (int ni = 0; ni < 4; ni++) {
            int n0 = cx.cb + ni * 8 + (lane & 3) * 2;
            float b0 = bs[n0], b1 = bs[n0 + 1];
            float a0 = acc[mi][ni][0] + b0, a1 = acc[mi][ni][1] + b1;
            float a2 = acc[mi][ni][2] + b0, a3 = acc[mi][ni][3] + b1;
            if (mode == 1 || mode == 2) {
                int hoff = ((n0 >> 2) << 3) + (n0 & 3) + ((mode == 2) ? 4 : 0);
                if (rA < n) *(__half2*)(g_kv + (size_t)rA * 256 + hoff) = __floats2half2_rn(a0, a1);
                if (rB < n) *(__half2*)(g_kv + (size_t)rB * 256 + hoff) = __floats2half2_rn(a2, a3);
            } else {
                if (rA < n) *(float2*)(g_q + (size_t)rA * HID + n0) = make_float2(a0 * scale, a1 * scale);
                if (rB < n) *(float2*)(g_q + (size_t)rB * HID + n0) = make_float2(a2 * scale, a3 * scale);
            }
        }
    }
}

// ---------------- CSR build ----------------
__global__ void hist_kernel(const int* __restrict__ rows, int e) {
    int i = blockIdx.x * blockDim.x + threadIdx.x;
    if (i < e) atomicAdd(&g_cnt[rows[i]], 1);
}
__global__ __launch_bounds__(256)
void scan1_kernel(int n) {
    __shared__ int wsum[8];
    const int tid = threadIdx.x;
    const int lane = tid & 31, w = tid >> 5;
    const int base = blockIdx.x * SCAN_CHUNK + tid * 4;
    int v[4];
#pragma unroll
    for (int j = 0; j < 4; j++) { int i = base + j; v[j] = (i < n) ? g_cnt[i] : 0; }
    int s = v[0] + v[1] + v[2] + v[3];
    int ps = s;
#pragma unroll
    for (int off = 1; off < 32; off <<= 1) {
        int t = __shfl_up_sync(0xffffffffu, ps, off);
        if (lane >= off) ps += t;
    }
    if (lane == 31) wsum[w] = ps;
    __syncthreads();
    if (w == 0) {
        int t = (lane < 8) ? wsum[lane] : 0;
#pragma unroll
        for (int off = 1; off < 8; off <<= 1) {
            int u = __shfl_up_sync(0xffffffffu, t, off);
            if (lane >= off) t += u;
        }
        if (lane < 8) wsum[lane] = t;
        if (lane == 7) g_bsum[blockIdx.x] = t;
    }
    __syncthreads();
    int excl = ps - s + ((w > 0) ? wsum[w - 1] : 0);
#pragma unroll
    for (int j = 0; j < 4; j++) {
        int i = base + j;
        if (i < n) g_rp[i] = excl;
        excl += v[j];
    }
}
__global__ void scan2_kernel(int nb, int n, int e) {
    int lane = threadIdx.x;
    int i0 = 2 * lane, i1 = 2 * lane + 1;
    int v0 = (i0 < nb) ? g_bsum[i0] : 0;
    int v1 = (i1 < nb) ? g_bsum[i1] : 0;
    int s = v0 + v1;
    int ps = s;
#pragma unroll
    for (int off = 1; off < 32; off <<= 1) {
        int t = __shfl_up_sync(0xffffffffu, ps, off);
        if (lane >= off) ps += t;
    }
    int excl = ps - s;
    if (i0 < nb) g_bsum[i0] = excl;
    if (i1 < nb) g_bsum[i1] = excl + v0;
    if (lane == 0) g_rp[n] = e;
}
__global__ void scan3_kernel(int n) {
    int i = blockIdx.x * blockDim.x + threadIdx.x;
    if (i < n) {
        int r = g_rp[i] + g_bsum[i / SCAN_CHUNK];
        g_rp[i] = r;
        g_cnt[i] = r;
    }
}
__global__ void scatter_kernel(const int* __restrict__ rows,
                               const int* __restrict__ cols, int e) {
    int i = blockIdx.x * blockDim.x + threadIdx.x;
    if (i < e) {
        int p = atomicAdd(&g_cnt[rows[i]], 1);
        g_col[p] = cols[i];
    }
}

// ---------------- FUSED attn + oproj ----------------
// Block: 512 threads / 16 warps, 128 rows. Warp w: attn for rows w*8..w*8+7,
// writing t directly into smem split-bf16 A planes; then block-wide mma with
// pre-staged Wo (mode 3) and epilogue to d_out.
__global__ __launch_bounds__(512, 1)
void attn_oproj_kernel(float* __restrict__ out, int n) {
    extern __shared__ char smem[];
    const uint32_t sb = smem_u32(smem);
    const int tid = threadIdx.x;
    const int wid = tid >> 5, lane = tid & 31;
    const int row0 = blockIdx.x * 128;

    if (tid < 128) *(float*)(smem + tid * 4) = g_biasp[3 * 128 + tid];

    // stage Wo images
    {
        const float4* sh = (const float4*)(g_wh + (size_t)3 * 128 * WSTR);
        const float4* sl = (const float4*)(g_wl + (size_t)3 * 128 * WSTR);
        float4* dh = (float4*)(smem + SM_WHI);
        float4* dl = (float4*)(smem + SM_WLO);
#pragma unroll
        for (int i = 0; i < 5; i++) {
            int idx = tid + 512 * i;
            if (idx < 2176) { dh[idx] = sh[idx]; dl[idx] = sl[idx]; }
        }
    }

    // attention: 8 rows per warp, t -> smem planes
    uint16_t* ahp0 = (uint16_t*)(smem + SM_AHI);
    uint16_t* alp0 = (uint16_t*)(smem + SM_ALO);
#pragma unroll 1
    for (int rr = 0; rr < 8; rr++) {
        int lr = wid * 8 + rr;
        int r  = row0 + lr;
        float4 o = make_float4(0.f, 0.f, 0.f, 0.f);
        if (r < n) {
            int beg = g_rp[r], end = g_rp[r + 1];
            float4 q4 = ((const float4*)(g_q + (size_t)r * HID))[lane];
            float s = 0.f, ax = 0.f, ay = 0.f, az = 0.f, aw = 0.f;
            int j = beg;
            for (; j + 4 <= end; j += 4) {
                int c0 = g_col[j], c1 = g_col[j + 1], c2 = g_col[j + 2], c3 = g_col[j + 3];
                uint4 kv0 = ((const uint4*)(g_kv + (size_t)c0 * 256))[lane];
                uint4 kv1 = ((const uint4*)(g_kv + (size_t)c1 * 256))[lane];
                uint4 kv2 = ((const uint4*)(g_kv + (size_t)c2 * 256))[lane];
                uint4 kv3 = ((const uint4*)(g_kv + (size_t)c3 * 256))[lane];

                float2 kA0 = __half22float2(*(__half2*)&kv0.x), kB0 = __half22float2(*(__half2*)&kv0.y);
                float2 kA1 = __half22float2(*(__half2*)&kv1.x), kB1 = __half22float2(*(__half2*)&kv1.y);
                float2 kA2 = __half22float2(*(__half2*)&kv2.x), kB2 = __half22float2(*(__half2*)&kv2.y);
                float2 kA3 = __half22float2(*(__half2*)&kv3.x), kB3 = __half22float2(*(__half2*)&kv3.y);

                float p0 = q4.x * kA0.x + q4.y * kA0.y + q4.z * kB0.x + q4.w * kB0.y;
                float p1 = q4.x * kA1.x + q4.y * kA1.y + q4.z * kB1.x + q4.w * kB1.y;
                float p2 = q4.x * kA2.x + q4.y * kA2.y + q4.z * kB2.x + q4.w * kB2.y;
                float p3 = q4.x * kA3.x + q4.y * kA3.y + q4.z * kB3.x + q4.w * kB3.y;
                p0 += __shfl_xor_sync(0xffffffffu, p0, 1);
                p1 += __shfl_xor_sync(0xffffffffu, p1, 1);
                p2 += __shfl_xor_sync(0xffffffffu, p2, 1);
                p3 += __shfl_xor_sync(0xffffffffu, p3, 1);
                p0 += __shfl_xor_sync(0xffffffffu, p0, 2);
                p1 += __shfl_xor_sync(0xffffffffu, p1, 2);
                p2 += __shfl_xor_sync(0xffffffffu, p2, 2);
                p3 += __shfl_xor_sync(0xffffffffu, p3, 2);

                float e0 = __expf(p0), e1 = __expf(p1), e2 = __expf(p2), e3 = __expf(p3);
                s += (e0 + e1) + (e2 + e3);
                float2 vA0 = __half22float2(*(__half2*)&kv0.z), vB0 = __half22float2(*(__half2*)&kv0.w);
                float2 vA1 = __half22float2(*(__half2*)&kv1.z), vB1 = __half22float2(*(__half2*)&kv1.w);
                float2 vA2 = __half22float2(*(__half2*)&kv2.z), vB2 = __half22float2(*(__half2*)&kv2.w);
                float2 vA3 = __half22float2(*(__half2*)&kv3.z), vB3 = __half22float2(*(__half2*)&kv3.w);
                ax += e0 * vA0.x + e1 * vA1.x + e2 * vA2.x + e3 * vA3.x;
                ay += e0 * vA0.y + e1 * vA1.y + e2 * vA2.y + e3 * vA3.y;
                az += e0 * vB0.x + e1 * vB1.x + e2 * vB2.x + e3 * vB3.x;
                aw += e0 * vB0.y + e1 * vB1.y + e2 * vB2.y + e3 * vB3.y;
            }
            for (; j < end; j++) {
                int c = g_col[j];
                uint4 kv = ((const uint4*)(g_kv + (size_t)c * 256))[lane];
                float2 kA = __half22float2(*(__half2*)&kv.x), kB = __half22float2(*(__half2*)&kv.y);
                float p = q4.x * kA.x + q4.y * kA.y + q4.z * kB.x + q4.w * kB.y;
                p += __shfl_xor_sync(0xffffffffu, p, 1);
                p += __shfl_xor_sync(0xffffffffu, p, 2);
                float e = __expf(p);
                s += e;
                float2 vA = __half22float2(*(__half2*)&kv.z), vB = __half22float2(*(__half2*)&kv.w);
                ax += e * vA.x; ay += e * vA.y; az += e * vB.x; aw += e * vB.y;
            }
            if (end > beg) {
                float inv = 1.0f / s;
                o = make_float4(ax * inv, ay * inv, az * inv, aw * inv);
            }
        }
        split_store_pair(ahp0 + lr * WSTR + lane * 4, alp0 + lr * WSTR + lane * 4, o);
    }
    __syncthreads();

    // oproj mma + epilogue
    MmaCtx cx;
    mma_setup(cx, sb, wid, lane);
    float acc[2][4][4];
    mma_mainloop(cx, acc);

    const float* bs = (const float*)smem;
#pragma unroll
    for (int mi = 0; mi < 2; mi++) {
        int rA = row0 + cx.Rw + mi * 16 + (lane >> 2);
        int rB = rA + 8;
#pragma unroll
        for (int ni = 0; ni < 4; ni++) {
            int n0 = cx.cb + ni * 8 + (lane & 3) * 2;
            float b0 = bs[n0], b1 = bs[n0 + 1];
            if (rA < n)
                *(float2*)(out + (size_t)rA * HID + n0) =
                    make_float2(acc[mi][ni][0] + b0, acc[mi][ni][1] + b1);
            if (rB < n)
                *(float2*)(out + (size_t)rB * HID + n0) =
                    make_float2(acc[mi][ni][2] + b0, acc[mi][ni][3] + b1);
        }
    }
}

// ---------------- launch ----------------
extern "C" void kernel_launch(void* const* d_in, const int* in_sizes, int n_in,
                              void* d_out, int out_size) {
    const float* h    = (const float*)d_in[0];
    const int*   rows = (const int*)  d_in[1];
    const int*   cols = (const int*)  d_in[2];
    const float* Wq = (const float*)d_in[3]; const float* bq = (const float*)d_in[4];
    const float* Wk = (const float*)d_in[5]; const float* bk = (const float*)d_in[6];
    const float* Wv = (const float*)d_in[7]; const float* bv = (const float*)d_in[8];
    const float* Wo = (const float*)d_in[9]; const float* bo = (const float*)d_in[10];
    float* out = (float*)d_out;

    int n = in_sizes[0] / HID;
    int e = in_sizes[1];

    cudaFuncSetAttribute(mma_gemm_kernel,  cudaFuncAttributeMaxDynamicSharedMemorySize, SM_TOTAL);
    cudaFuncSetAttribute(attn_oproj_kernel, cudaFuncAttributeMaxDynamicSharedMemorySize, SM_TOTAL);

    static cudaStream_t s2 = nullptr;
    static cudaEvent_t evFork = nullptr, evJoin = nullptr;
    if (!s2) {
        cudaStreamCreateWithFlags(&s2, cudaStreamNonBlocking);
        cudaEventCreateWithFlags(&evFork, cudaEventDisableTiming);
        cudaEventCreateWithFlags(&evJoin, cudaEventDisableTiming);
    }

    void* cnt_addr = nullptr;
    cudaGetSymbolAddress(&cnt_addr, g_cnt);

    cudaEventRecord(evFork, 0);
    cudaStreamWaitEvent(s2, evFork, 0);

    int nb = (n + SCAN_CHUNK - 1) / SCAN_CHUNK;
    cudaMemsetAsync(cnt_addr, 0, (size_t)n * sizeof(int), s2);
    hist_kernel<<<(e + 255) / 256, 256, 0, s2>>>(rows, e);
    scan1_kernel<<<nb, 256, 0, s2>>>(n);
    scan2_kernel<<<1, 32, 0, s2>>>(nb, n, e);
    scan3_kernel<<<(n + 255) / 256, 256, 0, s2>>>(n);
    scatter_kernel<<<(e + 255) / 256, 256, 0, s2>>>(rows, cols, e);

    prep_w_kernel<<<4, 256>>>(Wq, bq, Wk, bk, Wv, bv, Wo, bo);
    int nt = (n + 127) / 128;
    mma_gemm_kernel<<<dim3(nt, 3), 512, SM_TOTAL>>>(h, n);

    cudaEventRecord(evJoin, s2);
    cudaStreamWaitEvent(0, evJoin, 0);

    attn_oproj_kernel<<<nt, 512, SM_TOTAL>>>(out, n);
}

// round 16
// speedup vs baseline: 1.2325x; 1.2325x over previous
#include <cuda_runtime.h>
#include <cuda_fp16.h>
#include <math.h>
#include <stdint.h>

#define HID  128
#define NMAX 50000
#define EMAX 800000
#define SCAN_CHUNK 1024
#define WSTR 136          // padded row stride in fp16 halves (272B, 16B-aligned)

// ---------------- device scratch ----------------
__device__ float  g_q[NMAX * HID];        // fp32, head-major
// interleaved k/v, fp16: per node 32 chunks of 16B = {k[4i..4i+3], v[4i..4i+3]}
__device__ __half g_kv[NMAX * 256];
__device__ float  g_t[NMAX * HID];        // attn output (head-major)
__device__ int   g_cnt[NMAX];
__device__ int   g_rp[NMAX + 1];
__device__ int   g_col[EMAX];
__device__ int   g_bsum[64];
__device__ uint16_t g_wf[4 * 128 * WSTR];  // single-fp16 weight images
__device__ float    g_biasp[4 * 128];

__device__ __forceinline__ int permc(int c)  { return ((c & 7) << 4) | (c >> 3); }
__device__ __forceinline__ int ipermc(int j) { return ((j & 15) << 3) | (j >> 4); }

__device__ __forceinline__ uint32_t smem_u32(const void* p) {
    uint32_t a;
    asm("{ .reg .u64 t; cvta.to.shared.u64 t, %1; cvt.u32.u64 %0, t; }" : "=r"(a) : "l"(p));
    return a;
}
#define LDSM_X4(r0, r1, r2, r3, addr) \
    asm volatile("ldmatrix.sync.aligned.m8n8.x4.shared.b16 {%0,%1,%2,%3}, [%4];" \
                 : "=r"(r0), "=r"(r1), "=r"(r2), "=r"(r3) : "r"(addr))
#define MMA_F16(c, a, b) \
    asm volatile("mma.sync.aligned.m16n8k16.row.col.f32.f16.f16.f32 " \
                 "{%0,%1,%2,%3}, {%4,%5,%6,%7}, {%8,%9}, {%0,%1,%2,%3};" \
                 : "+f"((c)[0]), "+f"((c)[1]), "+f"((c)[2]), "+f"((c)[3]) \
                 : "r"((a)[0]), "r"((a)[1]), "r"((a)[2]), "r"((a)[3]), \
                   "r"((b)[0]), "r"((b)[1]))

// smem layout: bias(512) | A hi | A lo | W  (each 128*WSTR halves = 34816 B)
#define SM_TILE  (128 * WSTR * 2)
#define SM_AHI   1024
#define SM_ALO   (SM_AHI + SM_TILE)
#define SM_W     (SM_ALO + SM_TILE)
#define SM_TOTAL (SM_W + SM_TILE)          // 105472 B
#define W_F4     2176                      // float4 count of one 128*WSTR fp16 image

// ---------------- weight prep: fp32 -> single fp16 padded images ----------
__global__ void prep_w_kernel(const float* __restrict__ Wq, const float* __restrict__ bq,
                              const float* __restrict__ Wk, const float* __restrict__ bk,
                              const float* __restrict__ Wv, const float* __restrict__ bv,
                              const float* __restrict__ Wo, const float* __restrict__ bo) {
    int s = blockIdx.x;
    const float* W = (s == 0) ? Wq : (s == 1) ? Wk : (s == 2) ? Wv : Wo;
    const float* b = (s == 0) ? bq : (s == 1) ? bk : (s == 2) ? bv : bo;
    uint16_t* dw = g_wf + (size_t)s * 128 * WSTR;

    for (int idx = threadIdx.x; idx < 128 * 128; idx += blockDim.x) {
        int j = idx >> 7, k = idx & 127;
        float val; int dc;
        if (s < 3) { val = W[ipermc(j) * HID + k]; dc = k; }
        else       { val = W[j * HID + k];         dc = permc(k); }
        __half hv = __float2half_rn(val);
        dw[j * WSTR + dc] = __half_as_ushort(hv);
    }
    if (threadIdx.x < 128) {
        int j = threadIdx.x;
        g_biasp[s * 128 + j] = (s < 3) ? b[ipermc(j)] : b[j];
    }
}

// ---------------- helpers ----------------
__device__ __forceinline__ void split_store_pair_f16(uint16_t* hp, uint16_t* lp, float4 x) {
    __half h0 = __float2half_rn(x.x), h1 = __float2half_rn(x.y);
    __half h2 = __float2half_rn(x.z), h3 = __float2half_rn(x.w);
    __half l0 = __float2half_rn(x.x - __half2float(h0));
    __half l1 = __float2half_rn(x.y - __half2float(h1));
    __half l2 = __float2half_rn(x.z - __half2float(h2));
    __half l3 = __float2half_rn(x.w - __half2float(h3));
    uint32_t hA = ((uint32_t)__half_as_ushort(h1) << 16) | __half_as_ushort(h0);
    uint32_t hB = ((uint32_t)__half_as_ushort(h3) << 16) | __half_as_ushort(h2);
    uint32_t lA = ((uint32_t)__half_as_ushort(l1) << 16) | __half_as_ushort(l0);
    uint32_t lB = ((uint32_t)__half_as_ushort(l3) << 16) | __half_as_ushort(l2);
    *(uint2*)hp = make_uint2(hA, hB);
    *(uint2*)lp = make_uint2(lA, lB);
}

// ---------------- mma.sync GEMM: 512 threads, warp tile 32x32, 2-MMA split -
__global__ __launch_bounds__(512, 1)
void mma_gemm_kernel(const float* __restrict__ A_ext, float* __restrict__ out_ext,
                     int mode_base, int n) {
    extern __shared__ char smem[];
    const uint32_t sb = smem_u32(smem);
    const int tid = threadIdx.x;
    const int wid = tid >> 5, lane = tid & 31;
    const int mode = mode_base + blockIdx.y;
    const int row0 = blockIdx.x * 128;

    const float* A = (mode == 3) ? g_t : A_ext;
    const float scale = (mode == 0) ? 0.25f : 1.0f;

    if (tid < 128) *(float*)(smem + tid * 4) = g_biasp[mode * 128 + tid];

    // W copy: single prebuilt fp16 image (2176 float4 = 34816 B)
    {
        const float4* sw = (const float4*)(g_wf + (size_t)mode * 128 * WSTR);
        float4* dw = (float4*)(smem + SM_W);
#pragma unroll
        for (int i = 0; i < 5; i++) {
            int idx = tid + 512 * i;
            if (idx < W_F4) dw[idx] = sw[idx];
        }
    }
    // A fill: thread t -> row t>>2, quarter t&3 (32 cols); fp32 -> hi/lo fp16
    {
        int r = tid >> 2, hf = tid & 3;
        bool ok = (row0 + r) < n;
        const float4* arow = (const float4*)(A + (size_t)(row0 + r) * HID) + hf * 8;
        uint16_t* ahp = (uint16_t*)(smem + SM_AHI) + r * WSTR + hf * 32;
        uint16_t* alp = (uint16_t*)(smem + SM_ALO) + r * WSTR + hf * 32;
#pragma unroll
        for (int i = 0; i < 8; i++) {
            float4 x = ok ? arow[i] : make_float4(0.f, 0.f, 0.f, 0.f);
            split_store_pair_f16(ahp + i * 4, alp + i * 4, x);
        }
    }
    __syncthreads();

    // warp tile: rows Rw..Rw+31 (two m16), cols cb..cb+31 (four n8)
    const int Rw = (wid & 3) * 32;
    const int cb = (wid >> 2) * 32;

    const int a_r = Rw + (lane & 15);
    const int a_k = (lane >> 4) << 3;
    uint32_t aAddrH[2], aAddrL[2];
#pragma unroll
    for (int mi = 0; mi < 2; mi++) {
        uint32_t off = (uint32_t)((a_r + mi * 16) * WSTR + a_k) * 2;
        aAddrH[mi] = sb + SM_AHI + off;
        aAddrL[mi] = sb + SM_ALO + off;
    }
    const int b_r = (lane & 7) + ((lane >> 4) << 3);
    const int b_k = ((lane >> 3) & 1) << 3;
    uint32_t bAddr[2];
#pragma unroll
    for (int g = 0; g < 2; g++) {
        uint32_t off = (uint32_t)((cb + g * 16 + b_r) * WSTR + b_k) * 2;
        bAddr[g] = sb + SM_W + off;
    }

    float acc[2][4][4];
#pragma unroll
    for (int mi = 0; mi < 2; mi++)
#pragma unroll
        for (int ni = 0; ni < 4; ni++)
#pragma unroll
            for (int r = 0; r < 4; r++) acc[mi][ni][r] = 0.f;

#pragma unroll 2
    for (int k = 0; k < 8; k++) {
        const uint32_t ko = k * 32;
        uint32_t ah[2][4], al[2][4], bb[4][2];
#pragma unroll
        for (int mi = 0; mi < 2; mi++) {
            LDSM_X4(ah[mi][0], ah[mi][1], ah[mi][2], ah[mi][3], aAddrH[mi] + ko);
            LDSM_X4(al[mi][0], al[mi][1], al[mi][2], al[mi][3], aAddrL[mi] + ko);
        }
#pragma unroll
        for (int g = 0; g < 2; g++)
            LDSM_X4(bb[2 * g][0], bb[2 * g][1], bb[2 * g + 1][0], bb[2 * g + 1][1], bAddr[g] + ko);
#pragma unroll
        for (int mi = 0; mi < 2; mi++)
#pragma unroll
            for (int ni = 0; ni < 4; ni++) {
                MMA_F16(acc[mi][ni], ah[mi], bb[ni]);
                MMA_F16(acc[mi][ni], al[mi], bb[ni]);
            }
    }

    // epilogue: q/out -> fp32; k/v -> interleaved fp16 g_kv
    const float* bs = (const float*)smem;
    float* Cf = (mode == 0) ? g_q : out_ext;
#pragma unroll
    for (int mi = 0; mi < 2; mi++) {
        int rA = row0 + Rw + mi * 16 + (lane >> 2);
        int rB = rA + 8;
#pragma unroll
        for (int ni = 0; ni < 4; ni++) {
            int n0 = cb + ni * 8 + (lane & 3) * 2;
            float b0 = bs[n0], b1 = bs[n0 + 1];
            float a0 = acc[mi][ni][0] + b0, a1 = acc[mi][ni][1] + b1;
            float a2 = acc[mi][ni][2] + b0, a3 = acc[mi][ni][3] + b1;
            if (mode == 1 || mode == 2) {
                int hoff = ((n0 >> 2) << 3) + (n0 & 3) + ((mode == 2) ? 4 : 0);
                if (rA < n) *(__half2*)(g_kv + (size_t)rA * 256 + hoff) = __floats2half2_rn(a0, a1);
                if (rB < n) *(__half2*)(g_kv + (size_t)rB * 256 + hoff) = __floats2half2_rn(a2, a3);
            } else {
                if (rA < n) *(float2*)(Cf + (size_t)rA * HID + n0) = make_float2(a0 * scale, a1 * scale);
                if (rB < n) *(float2*)(Cf + (size_t)rB * HID + n0) = make_float2(a2 * scale, a3 * scale);
            }
        }
    }
}

// ---------------- CSR build ----------------
__global__ void hist_kernel(const int* __restrict__ rows, int e) {
    int i = blockIdx.x * blockDim.x + threadIdx.x;
    if (i < e) atomicAdd(&g_cnt[rows[i]], 1);
}
__global__ __launch_bounds__(256)
void scan1_kernel(int n) {
    __shared__ int wsum[8];
    const int tid = threadIdx.x;
    const int lane = tid & 31, w = tid >> 5;
    const int base = blockIdx.x * SCAN_CHUNK + tid * 4;
    int v[4];
#pragma unroll
    for (int j = 0; j < 4; j++) { int i = base + j; v[j] = (i < n) ? g_cnt[i] : 0; }
    int s = v[0] + v[1] + v[2] + v[3];
    int ps = s;
#pragma unroll
    for (int off = 1; off < 32; off <<= 1) {
        int t = __shfl_up_sync(0xffffffffu, ps, off);
        if (lane >= off) ps += t;
    }
    if (lane == 31) wsum[w] = ps;
    __syncthreads();
    if (w == 0) {
        int t = (lane < 8) ? wsum[lane] : 0;
#pragma unroll
        for (int off = 1; off < 8; off <<= 1) {
            int u = __shfl_up_sync(0xffffffffu, t, off);
            if (lane >= off) t += u;
        }
        if (lane < 8) wsum[lane] = t;
        if (lane == 7) g_bsum[blockIdx.x] = t;
    }
    __syncthreads();
    int excl = ps - s + ((w > 0) ? wsum[w - 1] : 0);
#pragma unroll
    for (int j = 0; j < 4; j++) {
        int i = base + j;
        if (i < n) g_rp[i] = excl;
        excl += v[j];
    }
}
__global__ void scan2_kernel(int nb, int n, int e) {
    int lane = threadIdx.x;
    int i0 = 2 * lane, i1 = 2 * lane + 1;
    int v0 = (i0 < nb) ? g_bsum[i0] : 0;
    int v1 = (i1 < nb) ? g_bsum[i1] : 0;
    int s = v0 + v1;
    int ps = s;
#pragma unroll
    for (int off = 1; off < 32; off <<= 1) {
        int t = __shfl_up_sync(0xffffffffu, ps, off);
        if (lane >= off) ps += t;
    }
    int excl = ps - s;
    if (i0 < nb) g_bsum[i0] = excl;
    if (i1 < nb) g_bsum[i1] = excl + v0;
    if (lane == 0) g_rp[n] = e;
}
__global__ void scan3_kernel(int n) {
    int i = blockIdx.x * blockDim.x + threadIdx.x;
    if (i < n) {
        int r = g_rp[i] + g_bsum[i / SCAN_CHUNK];
        g_rp[i] = r;
        g_cnt[i] = r;
    }
}
__global__ void scatter_kernel(const int* __restrict__ rows,
                               const int* __restrict__ cols, int e) {
    int i = blockIdx.x * blockDim.x + threadIdx.x;
    if (i < e) {
        int p = atomicAdd(&g_cnt[rows[i]], 1);
        g_col[p] = cols[i];
    }
}

// ---------------- fused SDDMM + softmax + SpMM (interleaved fp16 kv) ------
__global__ void attn_kernel(int n) {
    int w = (blockIdx.x * blockDim.x + threadIdx.x) >> 5;
    int lane = threadIdx.x & 31;
    if (w >= n) return;
    int beg = g_rp[w], end = g_rp[w + 1];

    float4 q4 = ((const float4*)(g_q + (size_t)w * HID))[lane];

    float s = 0.f, ax = 0.f, ay = 0.f, az = 0.f, aw = 0.f;

    int j = beg;
    for (; j + 4 <= end; j += 4) {
        int c0 = g_col[j], c1 = g_col[j + 1], c2 = g_col[j + 2], c3 = g_col[j + 3];
        uint4 kv0 = ((const uint4*)(g_kv + (size_t)c0 * 256))[lane];
        uint4 kv1 = ((const uint4*)(g_kv + (size_t)c1 * 256))[lane];
        uint4 kv2 = ((const uint4*)(g_kv + (size_t)c2 * 256))[lane];
        uint4 kv3 = ((const uint4*)(g_kv + (size_t)c3 * 256))[lane];

        float2 kA0 = __half22float2(*(__half2*)&kv0.x), kB0 = __half22float2(*(__half2*)&kv0.y);
        float2 kA1 = __half22float2(*(__half2*)&kv1.x), kB1 = __half22float2(*(__half2*)&kv1.y);
        float2 kA2 = __half22float2(*(__half2*)&kv2.x), kB2 = __half22float2(*(__half2*)&kv2.y);
        float2 kA3 = __half22float2(*(__half2*)&kv3.x), kB3 = __half22float2(*(__half2*)&kv3.y);

        float p0 = q4.x * kA0.x + q4.y * kA0.y + q4.z * kB0.x + q4.w * kB0.y;
        float p1 = q4.x * kA1.x + q4.y * kA1.y + q4.z * kB1.x + q4.w * kB1.y;
        float p2 = q4.x * kA2.x + q4.y * kA2.y + q4.z * kB2.x + q4.w * kB2.y;
        float p3 = q4.x * kA3.x + q4.y * kA3.y + q4.z * kB3.x + q4.w * kB3.y;
        p0 += __shfl_xor_sync(0xffffffffu, p0, 1);
        p1 += __shfl_xor_sync(0xffffffffu, p1, 1);
        p2 += __shfl_xor_sync(0xffffffffu, p2, 1);
        p3 += __shfl_xor_sync(0xffffffffu, p3, 1);
        p0 += __shfl_xor_sync(0xffffffffu, p0, 2);
        p1 += __shfl_xor_sync(0xffffffffu, p1, 2);
        p2 += __shfl_xor_sync(0xffffffffu, p2, 2);
        p3 += __shfl_xor_sync(0xffffffffu, p3, 2);

        float e0 = __expf(p0), e1 = __expf(p1), e2 = __expf(p2), e3 = __expf(p3);
        s += (e0 + e1) + (e2 + e3);
        float2 vA0 = __half22float2(*(__half2*)&kv0.z), vB0 = __half22float2(*(__half2*)&kv0.w);
        float2 vA1 = __half22float2(*(__half2*)&kv1.z), vB1 = __half22float2(*(__half2*)&kv1.w);
        float2 vA2 = __half22float2(*(__half2*)&kv2.z), vB2 = __half22float2(*(__half2*)&kv2.w);
        float2 vA3 = __half22float2(*(__half2*)&kv3.z), vB3 = __half22float2(*(__half2*)&kv3.w);
        ax += e0 * vA0.x + e1 * vA1.x + e2 * vA2.x + e3 * vA3.x;
        ay += e0 * vA0.y + e1 * vA1.y + e2 * vA2.y + e3 * vA3.y;
        az += e0 * vB0.x + e1 * vB1.x + e2 * vB2.x + e3 * vB3.x;
        aw += e0 * vB0.y + e1 * vB1.y + e2 * vB2.y + e3 * vB3.y;
    }
    for (; j < end; j++) {
        int c = g_col[j];
        uint4 kv = ((const uint4*)(g_kv + (size_t)c * 256))[lane];
        float2 kA = __half22float2(*(__half2*)&kv.x), kB = __half22float2(*(__half2*)&kv.y);
        float p = q4.x * kA.x + q4.y * kA.y + q4.z * kB.x + q4.w * kB.y;
        p += __shfl_xor_sync(0xffffffffu, p, 1);
        p += __shfl_xor_sync(0xffffffffu, p, 2);
        float e = __expf(p);
        s += e;
        float2 vA = __half22float2(*(__half2*)&kv.z), vB = __half22float2(*(__half2*)&kv.w);
        ax += e * vA.x; ay += e * vA.y; az += e * vB.x; aw += e * vB.y;
    }

    float4 o;
    if (end > beg) {
        float inv = 1.0f / s;
        o.x = ax * inv; o.y = ay * inv; o.z = az * inv; o.w = aw * inv;
    } else {
        o.x = o.y = o.z = o.w = 0.f;
    }
    ((float4*)(g_t + (size_t)w * HID))[lane] = o;
}

// ---------------- launch ----------------
extern "C" void kernel_launch(void* const* d_in, const int* in_sizes, int n_in,
                              void* d_out, int out_size) {
    const float* h    = (const float*)d_in[0];
    const int*   rows = (const int*)  d_in[1];
    const int*   cols = (const int*)  d_in[2];
    const float* Wq = (const float*)d_in[3]; const float* bq = (const float*)d_in[4];
    const float* Wk = (const float*)d_in[5]; const float* bk = (const float*)d_in[6];
    const float* Wv = (const float*)d_in[7]; const float* bv = (const float*)d_in[8];
    const float* Wo = (const float*)d_in[9]; const float* bo = (const float*)d_in[10];
    float* out = (float*)d_out;

    int n = in_sizes[0] / HID;
    int e = in_sizes[1];

    cudaFuncSetAttribute(mma_gemm_kernel, cudaFuncAttributeMaxDynamicSharedMemorySize, SM_TOTAL);

    static cudaStream_t s2 = nullptr;
    static cudaEvent_t evFork = nullptr, evJoin = nullptr;
    if (!s2) {
        cudaStreamCreateWithFlags(&s2, cudaStreamNonBlocking);
        cudaEventCreateWithFlags(&evFork, cudaEventDisableTiming);
        cudaEventCreateWithFlags(&evJoin, cudaEventDisableTiming);
    }

    void* cnt_addr = nullptr;
    cudaGetSymbolAddress(&cnt_addr, g_cnt);

    cudaEventRecord(evFork, 0);
    cudaStreamWaitEvent(s2, evFork, 0);

    int nb = (n + SCAN_CHUNK - 1) / SCAN_CHUNK;
    cudaMemsetAsync(cnt_addr, 0, (size_t)n * sizeof(int), s2);
    hist_kernel<<<(e + 255) / 256, 256, 0, s2>>>(rows, e);
    scan1_kernel<<<nb, 256, 0, s2>>>(n);
    scan2_kernel<<<1, 32, 0, s2>>>(nb, n, e);
    scan3_kernel<<<(n + 255) / 256, 256, 0, s2>>>(n);
    scatter_kernel<<<(e + 255) / 256, 256, 0, s2>>>(rows, cols, e);

    prep_w_kernel<<<4, 256>>>(Wq, bq, Wk, bk, Wv, bv, Wo, bo);
    int nt = (n + 127) / 128;
    mma_gemm_kernel<<<dim3(nt, 3), 512, SM_TOTAL>>>(h, nullptr, 0, n);

    cudaEventRecord(evJoin, s2);
    cudaStreamWaitEvent(0, evJoin, 0);

    attn_kernel<<<(n * 32 + 255) / 256, 256>>>(n);

    mma_gemm_kernel<<<dim3(nt, 1), 512, SM_TOTAL>>>(nullptr, out, 3, n);
}

// round 17
// speedup vs baseline: 1.5646x; 1.2694x over previous
#include <cuda_runtime.h>
#include <cuda_fp16.h>
#include <math.h>
#include <stdint.h>

#define HID  128
#define NMAX 50000
#define EMAX 800000
#define SCAN_CHUNK 1024
#define WSTR 136          // padded row stride in fp16 halves (272B, 16B-aligned)

// ---------------- device scratch ----------------
__device__ float  g_q[NMAX * HID];        // fp32, head-major
// interleaved k/v, fp16: per node 32 chunks of 16B = {k[4i..4i+3], v[4i..4i+3]}
__device__ __half g_kv[NMAX * 256];
__device__ float  g_t[NMAX * HID];        // attn output (head-major)
__device__ int   g_cnt[NMAX];
__device__ int   g_rp[NMAX + 1];
__device__ int   g_col[EMAX];
__device__ int   g_bsum[64];
__device__ uint16_t g_wf[4 * 128 * WSTR];  // single-fp16 weight images
__device__ float    g_biasp[4 * 128];

__device__ __forceinline__ int permc(int c)  { return ((c & 7) << 4) | (c >> 3); }
__device__ __forceinline__ int ipermc(int j) { return ((j & 15) << 3) | (j >> 4); }

__device__ __forceinline__ uint32_t smem_u32(const void* p) {
    uint32_t a;
    asm("{ .reg .u64 t; cvta.to.shared.u64 t, %1; cvt.u32.u64 %0, t; }" : "=r"(a) : "l"(p));
    return a;
}
#define LDSM_X4(r0, r1, r2, r3, addr) \
    asm volatile("ldmatrix.sync.aligned.m8n8.x4.shared.b16 {%0,%1,%2,%3}, [%4];" \
                 : "=r"(r0), "=r"(r1), "=r"(r2), "=r"(r3) : "r"(addr))
#define MMA_F16(c, a, b) \
    asm volatile("mma.sync.aligned.m16n8k16.row.col.f32.f16.f16.f32 " \
                 "{%0,%1,%2,%3}, {%4,%5,%6,%7}, {%8,%9}, {%0,%1,%2,%3};" \
                 : "+f"((c)[0]), "+f"((c)[1]), "+f"((c)[2]), "+f"((c)[3]) \
                 : "r"((a)[0]), "r"((a)[1]), "r"((a)[2]), "r"((a)[3]), \
                   "r"((b)[0]), "r"((b)[1]))

// smem layout: bias[3*128 floats] | A hi | A lo | W  (each plane 34816 B)
#define SM_TILE  (128 * WSTR * 2)
#define SM_AHI   2048
#define SM_ALO   (SM_AHI + SM_TILE)
#define SM_W     (SM_ALO + SM_TILE)
#define SM_TOTAL (SM_W + SM_TILE)          // 106496 B
#define W_F4     2176                      // float4 count of one 128*WSTR fp16 image

// ---------------- weight prep: fp32 -> single fp16 padded images ----------
__global__ void prep_w_kernel(const float* __restrict__ Wq, const float* __restrict__ bq,
                              const float* __restrict__ Wk, const float* __restrict__ bk,
                              const float* __restrict__ Wv, const float* __restrict__ bv,
                              const float* __restrict__ Wo, const float* __restrict__ bo) {
    int s = blockIdx.x;
    const float* W = (s == 0) ? Wq : (s == 1) ? Wk : (s == 2) ? Wv : Wo;
    const float* b = (s == 0) ? bq : (s == 1) ? bk : (s == 2) ? bv : bo;
    uint16_t* dw = g_wf + (size_t)s * 128 * WSTR;

    for (int idx = threadIdx.x; idx < 128 * 128; idx += blockDim.x) {
        int j = idx >> 7, k = idx & 127;
        float val; int dc;
        if (s < 3) { val = W[ipermc(j) * HID + k]; dc = k; }
        else       { val = W[j * HID + k];         dc = permc(k); }
        __half hv = __float2half_rn(val);
        dw[j * WSTR + dc] = __half_as_ushort(hv);
    }
    if (threadIdx.x < 128) {
        int j = threadIdx.x;
        g_biasp[s * 128 + j] = (s < 3) ? b[ipermc(j)] : b[j];
    }
}

// ---------------- helpers ----------------
__device__ __forceinline__ void split_store_pair_f16(uint16_t* hp, uint16_t* lp, float4 x) {
    __half h0 = __float2half_rn(x.x), h1 = __float2half_rn(x.y);
    __half h2 = __float2half_rn(x.z), h3 = __float2half_rn(x.w);
    __half l0 = __float2half_rn(x.x - __half2float(h0));
    __half l1 = __float2half_rn(x.y - __half2float(h1));
    __half l2 = __float2half_rn(x.z - __half2float(h2));
    __half l3 = __float2half_rn(x.w - __half2float(h3));
    uint32_t hA = ((uint32_t)__half_as_ushort(h1) << 16) | __half_as_ushort(h0);
    uint32_t hB = ((uint32_t)__half_as_ushort(h3) << 16) | __half_as_ushort(h2);
    uint32_t lA = ((uint32_t)__half_as_ushort(l1) << 16) | __half_as_ushort(l0);
    uint32_t lB = ((uint32_t)__half_as_ushort(l3) << 16) | __half_as_ushort(l2);
    *(uint2*)hp = make_uint2(hA, hB);
    *(uint2*)lp = make_uint2(lA, lB);
}

struct MmaAddr {
    uint32_t aH[2], aL[2], b[2];
    int Rw, cb;
};
__device__ __forceinline__ void mma_addr_setup(MmaAddr& cx, uint32_t sb, int wid, int lane) {
    cx.Rw = (wid & 3) * 32;
    cx.cb = (wid >> 2) * 32;
    const int a_r = cx.Rw + (lane & 15);
    const int a_k = (lane >> 4) << 3;
#pragma unroll
    for (int mi = 0; mi < 2; mi++) {
        uint32_t off = (uint32_t)((a_r + mi * 16) * WSTR + a_k) * 2;
        cx.aH[mi] = sb + SM_AHI + off;
        cx.aL[mi] = sb + SM_ALO + off;
    }
    const int b_r = (lane & 7) + ((lane >> 4) << 3);
    const int b_k = ((lane >> 3) & 1) << 3;
#pragma unroll
    for (int g = 0; g < 2; g++) {
        uint32_t off = (uint32_t)((cx.cb + g * 16 + b_r) * WSTR + b_k) * 2;
        cx.b[g] = sb + SM_W + off;
    }
}
__device__ __forceinline__ void mma_mainloop2(const MmaAddr& cx, float acc[2][4][4]) {
#pragma unroll
    for (int mi = 0; mi < 2; mi++)
#pragma unroll
        for (int ni = 0; ni < 4; ni++)
#pragma unroll
            for (int r = 0; r < 4; r++) acc[mi][ni][r] = 0.f;
#pragma unroll 2
    for (int k = 0; k < 8; k++) {
        const uint32_t ko = k * 32;
        uint32_t ah[2][4], al[2][4], bb[4][2];
#pragma unroll
        for (int mi = 0; mi < 2; mi++) {
            LDSM_X4(ah[mi][0], ah[mi][1], ah[mi][2], ah[mi][3], cx.aH[mi] + ko);
            LDSM_X4(al[mi][0], al[mi][1], al[mi][2], al[mi][3], cx.aL[mi] + ko);
        }
#pragma unroll
        for (int g = 0; g < 2; g++)
            LDSM_X4(bb[2 * g][0], bb[2 * g][1], bb[2 * g + 1][0], bb[2 * g + 1][1], cx.b[g] + ko);
#pragma unroll
        for (int mi = 0; mi < 2; mi++)
#pragma unroll
            for (int ni = 0; ni < 4; ni++) {
                MMA_F16(acc[mi][ni], ah[mi], bb[ni]);
                MMA_F16(acc[mi][ni], al[mi], bb[ni]);
            }
    }
}
__device__ __forceinline__ void copy_w_image(char* smem, int mode, int tid) {
    const float4* sw = (const float4*)(g_wf + (size_t)mode * 128 * WSTR);
    float4* dw = (float4*)(smem + SM_W);
#pragma unroll
    for (int i = 0; i < 5; i++) {
        int idx = tid + 512 * i;
        if (idx < W_F4) dw[idx] = sw[idx];
    }
}
__device__ __forceinline__ void fill_a_planes(char* smem, const float* __restrict__ A,
                                              int row0, int n, int tid) {
    int r = tid >> 2, hf = tid & 3;
    bool ok = (row0 + r) < n;
    const float4* arow = (const float4*)(A + (size_t)(row0 + r) * HID) + hf * 8;
    uint16_t* ahp = (uint16_t*)(smem + SM_AHI) + r * WSTR + hf * 32;
    uint16_t* alp = (uint16_t*)(smem + SM_ALO) + r * WSTR + hf * 32;
#pragma unroll
    for (int i = 0; i < 8; i++) {
        float4 x = ok ? arow[i] : make_float4(0.f, 0.f, 0.f, 0.f);
        split_store_pair_f16(ahp + i * 4, alp + i * 4, x);
    }
}

// ---------------- fused QKV GEMM: one A fill, 3 W passes ------------------
__global__ __launch_bounds__(512, 1)
void qkv_fused_kernel(const float* __restrict__ h, int n) {
    extern __shared__ char smem[];
    const uint32_t sb = smem_u32(smem);
    const int tid = threadIdx.x;
    const int wid = tid >> 5, lane = tid & 31;
    const int row0 = blockIdx.x * 128;

    if (tid < 384) *(float*)(smem + tid * 4) = g_biasp[tid];
    fill_a_planes(smem, h, row0, n, tid);

    MmaAddr cx;
    mma_addr_setup(cx, sb, wid, lane);

#pragma unroll 1
    for (int mode = 0; mode < 3; mode++) {
        copy_w_image(smem, mode, tid);
        __syncthreads();

        float acc[2][4][4];
        mma_mainloop2(cx, acc);

        const float* bs = (const float*)smem + mode * 128;
        const float scale = (mode == 0) ? 0.25f : 1.0f;
#pragma unroll
        for (int mi = 0; mi < 2; mi++) {
            int rA = row0 + cx.Rw + mi * 16 + (lane >> 2);
            int rB = rA + 8;
#pragma unroll
            for (int ni = 0; ni < 4; ni++) {
                int n0 = cx.cb + ni * 8 + (lane & 3) * 2;
                float b0 = bs[n0], b1 = bs[n0 + 1];
                float a0 = acc[mi][ni][0] + b0, a1 = acc[mi][ni][1] + b1;
                float a2 = acc[mi][ni][2] + b0, a3 = acc[mi][ni][3] + b1;
                if (mode == 0) {
                    if (rA < n) *(float2*)(g_q + (size_t)rA * HID + n0) = make_float2(a0 * scale, a1 * scale);
                    if (rB < n) *(float2*)(g_q + (size_t)rB * HID + n0) = make_float2(a2 * scale, a3 * scale);
                } else {
                    int hoff = ((n0 >> 2) << 3) + (n0 & 3) + ((mode == 2) ? 4 : 0);
                    if (rA < n) *(__half2*)(g_kv + (size_t)rA * 256 + hoff) = __floats2half2_rn(a0, a1);
                    if (rB < n) *(__half2*)(g_kv + (size_t)rB * 256 + hoff) = __floats2half2_rn(a2, a3);
                }
            }
        }
        __syncthreads();   // before overwriting W for next mode
    }
}

// ---------------- oproj GEMM (mode 3) ----------------
__global__ __launch_bounds__(512, 1)
void oproj_kernel(float* __restrict__ out, int n) {
    extern __shared__ char smem[];
    const uint32_t sb = smem_u32(smem);
    const int tid = threadIdx.x;
    const int wid = tid >> 5, lane = tid & 31;
    const int row0 = blockIdx.x * 128;

    if (tid < 128) *(float*)(smem + tid * 4) = g_biasp[3 * 128 + tid];
    copy_w_image(smem, 3, tid);
    fill_a_planes(smem, g_t, row0, n, tid);
    __syncthreads();

    MmaAddr cx;
    mma_addr_setup(cx, sb, wid, lane);
    float acc[2][4][4];
    mma_mainloop2(cx, acc);

    const float* bs = (const float*)smem;
#pragma unroll
    for (int mi = 0; mi < 2; mi++) {
        int rA = row0 + cx.Rw + mi * 16 + (lane >> 2);
        int rB = rA + 8;
#pragma unroll
        for (int ni = 0; ni < 4; ni++) {
            int n0 = cx.cb + ni * 8 + (lane & 3) * 2;
            float b0 = bs[n0], b1 = bs[n0 + 1];
            if (rA < n)
                *(float2*)(out + (size_t)rA * HID + n0) =
                    make_float2(acc[mi][ni][0] + b0, acc[mi][ni][1] + b1);
            if (rB < n)
                *(float2*)(out + (size_t)rB * HID + n0) =
                    make_float2(acc[mi][ni][2] + b0, acc[mi][ni][3] + b1);
        }
    }
}

// ---------------- CSR build ----------------
__global__ void hist_kernel(const int* __restrict__ rows, int e) {
    int i = blockIdx.x * blockDim.x + threadIdx.x;
    if (i < e) atomicAdd(&g_cnt[rows[i]], 1);
}
__global__ __launch_bounds__(256)
void scan1_kernel(int n) {
    __shared__ int wsum[8];
    const int tid = threadIdx.x;
    const int lane = tid & 31, w = tid >> 5;
    const int base = blockIdx.x * SCAN_CHUNK + tid * 4;
    int v[4];
#pragma unroll
    for (int j = 0; j < 4; j++) { int i = base + j; v[j] = (i < n) ? g_cnt[i] : 0; }
    int s = v[0] + v[1] + v[2] + v[3];
    int ps = s;
#pragma unroll
    for (int off = 1; off < 32; off <<= 1) {
        int t = __shfl_up_sync(0xffffffffu, ps, off);
        if (lane >= off) ps += t;
    }
    if (lane == 31) wsum[w] = ps;
    __syncthreads();
    if (w == 0) {
        int t = (lane < 8) ? wsum[lane] : 0;
#pragma unroll
        for (int off = 1; off < 8; off <<= 1) {
            int u = __shfl_up_sync(0xffffffffu, t, off);
            if (lane >= off) t += u;
        }
        if (lane < 8) wsum[lane] = t;
        if (lane == 7) g_bsum[blockIdx.x] = t;
    }
    __syncthreads();
    int excl = ps - s + ((w > 0) ? wsum[w - 1] : 0);
#pragma unroll
    for (int j = 0; j < 4; j++) {
        int i = base + j;
        if (i < n) g_rp[i] = excl;
        excl += v[j];
    }
}
__global__ void scan2_kernel(int nb, int n, int e) {
    int lane = threadIdx.x;
    int i0 = 2 * lane, i1 = 2 * lane + 1;
    int v0 = (i0 < nb) ? g_bsum[i0] : 0;
    int v1 = (i1 < nb) ? g_bsum[i1] : 0;
    int s = v0 + v1;
    int ps = s;
#pragma unroll
    for (int off = 1; off < 32; off <<= 1) {
        int t = __shfl_up_sync(0xffffffffu, ps, off);
        if (lane >= off) ps += t;
    }
    int excl = ps - s;
    if (i0 < nb) g_bsum[i0] = excl;
    if (i1 < nb) g_bsum[i1] = excl + v0;
    if (lane == 0) g_rp[n] = e;
}
__global__ void scan3_kernel(int n) {
    int i = blockIdx.x * blockDim.x + threadIdx.x;
    if (i < n) {
        int r = g_rp[i] + g_bsum[i / SCAN_CHUNK];
        g_rp[i] = r;
        g_cnt[i] = r;
    }
}
__global__ void scatter_kernel(const int* __restrict__ rows,
                               const int* __restrict__ cols, int e) {
    int i = blockIdx.x * blockDim.x + threadIdx.x;
    if (i < e) {
        int p = atomicAdd(&g_cnt[rows[i]], 1);
        g_col[p] = cols[i];
    }
}

// ---------------- fused SDDMM + softmax + SpMM (interleaved fp16 kv) ------
__global__ void attn_kernel(int n) {
    int w = (blockIdx.x * blockDim.x + threadIdx.x) >> 5;
    int lane = threadIdx.x & 31;
    if (w >= n) return;
    int beg = g_rp[w], end = g_rp[w + 1];

    float4 q4 = ((const float4*)(g_q + (size_t)w * HID))[lane];

    float s = 0.f, ax = 0.f, ay = 0.f, az = 0.f, aw = 0.f;

    int j = beg;
    for (; j + 4 <= end; j += 4) {
        int c0 = g_col[j], c1 = g_col[j + 1], c2 = g_col[j + 2], c3 = g_col[j + 3];
        uint4 kv0 = ((const uint4*)(g_kv + (size_t)c0 * 256))[lane];
        uint4 kv1 = ((const uint4*)(g_kv + (size_t)c1 * 256))[lane];
        uint4 kv2 = ((const uint4*)(g_kv + (size_t)c2 * 256))[lane];
        uint4 kv3 = ((const uint4*)(g_kv + (size_t)c3 * 256))[lane];

        float2 kA0 = __half22float2(*(__half2*)&kv0.x), kB0 = __half22float2(*(__half2*)&kv0.y);
        float2 kA1 = __half22float2(*(__half2*)&kv1.x), kB1 = __half22float2(*(__half2*)&kv1.y);
        float2 kA2 = __half22float2(*(__half2*)&kv2.x), kB2 = __half22float2(*(__half2*)&kv2.y);
        float2 kA3 = __half22float2(*(__half2*)&kv3.x), kB3 = __half22float2(*(__half2*)&kv3.y);

        float p0 = q4.x * kA0.x + q4.y * kA0.y + q4.z * kB0.x + q4.w * kB0.y;
        float p1 = q4.x * kA1.x + q4.y * kA1.y + q4.z * kB1.x + q4.w * kB1.y;
        float p2 = q4.x * kA2.x + q4.y * kA2.y + q4.z * kB2.x + q4.w * kB2.y;
        float p3 = q4.x * kA3.x + q4.y * kA3.y + q4.z * kB3.x + q4.w * kB3.y;
        p0 += __shfl_xor_sync(0xffffffffu, p0, 1);
        p1 += __shfl_xor_sync(0xffffffffu, p1, 1);
        p2 += __shfl_xor_sync(0xffffffffu, p2, 1);
        p3 += __shfl_xor_sync(0xffffffffu, p3, 1);
        p0 += __shfl_xor_sync(0xffffffffu, p0, 2);
        p1 += __shfl_xor_sync(0xffffffffu, p1, 2);
        p2 += __shfl_xor_sync(0xffffffffu, p2, 2);
        p3 += __shfl_xor_sync(0xffffffffu, p3, 2);

        float e0 = __expf(p0), e1 = __expf(p1), e2 = __expf(p2), e3 = __expf(p3);
        s += (e0 + e1) + (e2 + e3);
        float2 vA0 = __half22float2(*(__half2*)&kv0.z), vB0 = __half22float2(*(__half2*)&kv0.w);
        float2 vA1 = __half22float2(*(__half2*)&kv1.z), vB1 = __half22float2(*(__half2*)&kv1.w);
        float2 vA2 = __half22float2(*(__half2*)&kv2.z), vB2 = __half22float2(*(__half2*)&kv2.w);
        float2 vA3 = __half22float2(*(__half2*)&kv3.z), vB3 = __half22float2(*(__half2*)&kv3.w);
        ax += e0 * vA0.x + e1 * vA1.x + e2 * vA2.x + e3 * vA3.x;
        ay += e0 * vA0.y + e1 * vA1.y + e2 * vA2.y + e3 * vA3.y;
        az += e0 * vB0.x + e1 * vB1.x + e2 * vB2.x + e3 * vB3.x;
        aw += e0 * vB0.y + e1 * vB1.y + e2 * vB2.y + e3 * vB3.y;
    }
    for (; j < end; j++) {
        int c = g_col[j];
        uint4 kv = ((const uint4*)(g_kv + (size_t)c * 256))[lane];
        float2 kA = __half22float2(*(__half2*)&kv.x), kB = __half22float2(*(__half2*)&kv.y);
        float p = q4.x * kA.x + q4.y * kA.y + q4.z * kB.x + q4.w * kB.y;
        p += __shfl_xor_sync(0xffffffffu, p, 1);
        p += __shfl_xor_sync(0xffffffffu, p, 2);
        float e = __expf(p);
        s += e;
        float2 vA = __half22float2(*(__half2*)&kv.z), vB = __half22float2(*(__half2*)&kv.w);
        ax += e * vA.x; ay += e * vA.y; az += e * vB.x; aw += e * vB.y;
    }

    float4 o;
    if (end > beg) {
        float inv = 1.0f / s;
        o.x = ax * inv; o.y = ay * inv; o.z = az * inv; o.w = aw * inv;
    } else {
        o.x = o.y = o.z = o.w = 0.f;
    }
    ((float4*)(g_t + (size_t)w * HID))[lane] = o;
}

// ---------------- launch ----------------
extern "C" void kernel_launch(void* const* d_in, const int* in_sizes, int n_in,
                              void* d_out, int out_size) {
    const float* h    = (const float*)d_in[0];
    const int*   rows = (const int*)  d_in[1];
    const int*   cols = (const int*)  d_in[2];
    const float* Wq = (const float*)d_in[3]; const float* bq = (const float*)d_in[4];
    const float* Wk = (const float*)d_in[5]; const float* bk = (const float*)d_in[6];
    const float* Wv = (const float*)d_in[7]; const float* bv = (const float*)d_in[8];
    const float* Wo = (const float*)d_in[9]; const float* bo = (const float*)d_in[10];
    float* out = (float*)d_out;

    int n = in_sizes[0] / HID;
    int e = in_sizes[1];

    cudaFuncSetAttribute(qkv_fused_kernel, cudaFuncAttributeMaxDynamicSharedMemorySize, SM_TOTAL);
    cudaFuncSetAttribute(oproj_kernel,     cudaFuncAttributeMaxDynamicSharedMemorySize, SM_TOTAL);

    static cudaStream_t s2 = nullptr;
    static cudaEvent_t evFork = nullptr, evJoin = nullptr;
    if (!s2) {
        cudaStreamCreateWithFlags(&s2, cudaStreamNonBlocking);
        cudaEventCreateWithFlags(&evFork, cudaEventDisableTiming);
        cudaEventCreateWithFlags(&evJoin, cudaEventDisableTiming);
    }

    void* cnt_addr = nullptr;
    cudaGetSymbolAddress(&cnt_addr, g_cnt);

    cudaEventRecord(evFork, 0);
    cudaStreamWaitEvent(s2, evFork, 0);

    int nb = (n + SCAN_CHUNK - 1) / SCAN_CHUNK;
    cudaMemsetAsync(cnt_addr, 0, (size_t)n * sizeof(int), s2);
    hist_kernel<<<(e + 255) / 256, 256, 0, s2>>>(rows, e);
    scan1_kernel<<<nb, 256, 0, s2>>>(n);
    scan2_kernel<<<1, 32, 0, s2>>>(nb, n, e);
    scan3_kernel<<<(n + 255) / 256, 256, 0, s2>>>(n);
    scatter_kernel<<<(e + 255) / 256, 256, 0, s2>>>(rows, cols, e);

    prep_w_kernel<<<4, 1024>>>(Wq, bq, Wk, bk, Wv, bv, Wo, bo);
    int nt = (n + 127) / 128;
    qkv_fused_kernel<<<nt, 512, SM_TOTAL>>>(h, n);

    cudaEventRecord(evJoin, s2);
    cudaStreamWaitEvent(0, evJoin, 0);

    attn_kernel<<<(n * 32 + 255) / 256, 256>>>(n);

    oproj_kernel<<<nt, 512, SM_TOTAL>>>(out, n);
}